// round 14
// baseline (speedup 1.0000x reference)
#include <cuda_runtime.h>
#include <cuda_bf16.h>
#include <cstdint>

// ---------------------------------------------------------------------------
// B=2, S=2048, D=1024, H=16, HD=64, RANK=8, ALPHA=8
// ---------------------------------------------------------------------------

__device__ __align__(256) float g_xa [4096 * 8];
__device__ __align__(256) __nv_bfloat16 g_xh [4096 * 1024];
__device__ __align__(256) __nv_bfloat16 g_xl [4096 * 1024];
__device__ __align__(256) __nv_bfloat16 g_wqh[3072 * 1024];
__device__ __align__(256) __nv_bfloat16 g_wql[3072 * 1024];
__device__ __align__(256) __nv_bfloat16 g_wph[1024 * 1024];
__device__ __align__(256) __nv_bfloat16 g_wpl[1024 * 1024];
__device__ __align__(256) __nv_bfloat16 g_qh [4096 * 3072];
__device__ __align__(256) __nv_bfloat16 g_ql [4096 * 3072];
__device__ __align__(256) __nv_bfloat16 g_ch [4096 * 1024];
__device__ __align__(256) __nv_bfloat16 g_cl [4096 * 1024];

// ------------------------------ asm helpers --------------------------------
__device__ __forceinline__ uint32_t smem_u32(const void* p) {
    uint32_t a;
    asm("{ .reg .u64 t; cvta.to.shared.u64 t, %1; cvt.u32.u64 %0, t; }"
        : "=r"(a) : "l"(p));
    return a;
}
#define LDSM_X4(r0, r1, r2, r3, addr)                                     \
    asm volatile("ldmatrix.sync.aligned.m8n8.x4.shared.b16 "              \
                 "{%0,%1,%2,%3}, [%4];"                                   \
                 : "=r"(r0), "=r"(r1), "=r"(r2), "=r"(r3) : "r"(addr))
#define LDSM_X4_T(r0, r1, r2, r3, addr)                                   \
    asm volatile("ldmatrix.sync.aligned.m8n8.x4.trans.shared.b16 "        \
                 "{%0,%1,%2,%3}, [%4];"                                   \
                 : "=r"(r0), "=r"(r1), "=r"(r2), "=r"(r3) : "r"(addr))
#define CP_ASYNC16(dst, src)                                              \
    asm volatile("cp.async.cg.shared.global [%0], [%1], 16;"              \
                 :: "r"(dst), "l"(src))
#define CP_COMMIT()  asm volatile("cp.async.commit_group;")
#define CP_WAIT(n)   asm volatile("cp.async.wait_group %0;" :: "n"(n))

__device__ __forceinline__ void mma16816(float* c,
                                         uint32_t a0, uint32_t a1,
                                         uint32_t a2, uint32_t a3,
                                         uint32_t b0, uint32_t b1)
{
    asm volatile(
        "mma.sync.aligned.m16n8k16.row.col.f32.bf16.bf16.f32 "
        "{%0,%1,%2,%3}, {%4,%5,%6,%7}, {%8,%9}, {%0,%1,%2,%3};"
        : "+f"(c[0]), "+f"(c[1]), "+f"(c[2]), "+f"(c[3])
        : "r"(a0), "r"(a1), "r"(a2), "r"(a3), "r"(b0), "r"(b1));
}

__device__ __forceinline__ void split2(float x, float y, uint32_t& h, uint32_t& l)
{
    __nv_bfloat16 hx = __float2bfloat16(x);
    __nv_bfloat16 hy = __float2bfloat16(y);
    __nv_bfloat16 lx = __float2bfloat16(x - __bfloat162float(hx));
    __nv_bfloat16 ly = __float2bfloat16(y - __bfloat162float(hy));
    __nv_bfloat162 hp, lp;
    hp.x = hx; hp.y = hy;
    lp.x = lx; lp.y = ly;
    h = *(uint32_t*)&hp;
    l = *(uint32_t*)&lp;
}

// ---------------------------------------------------------------------------
// fused prep for x: bf16 hi/lo split + xa = x @ A_lora
// ---------------------------------------------------------------------------
__global__ __launch_bounds__(256) void split_xa(const float4* __restrict__ x,
                                                const float* __restrict__ Al,
                                                __nv_bfloat162* __restrict__ h,
                                                __nv_bfloat162* __restrict__ l,
                                                float* __restrict__ xa)
{
    const int m = blockIdx.x, tid = threadIdx.x;
    const int i = m * 256 + tid;
    float4 v = x[i];
    uint32_t h0, l0, h1, l1;
    split2(v.x, v.y, h0, l0);
    split2(v.z, v.w, h1, l1);
    h[2 * i]     = *(__nv_bfloat162*)&h0;
    h[2 * i + 1] = *(__nv_bfloat162*)&h1;
    l[2 * i]     = *(__nv_bfloat162*)&l0;
    l[2 * i + 1] = *(__nv_bfloat162*)&l1;

    float acc[8];
#pragma unroll
    for (int r = 0; r < 8; r++) acc[r] = 0.f;
    const int k0 = tid * 4;
    const float* vv = &v.x;
#pragma unroll
    for (int e = 0; e < 4; e++) {
        const float xv = vv[e];
        const float4 a0 = *(const float4*)(Al + (size_t)(k0 + e) * 8);
        const float4 a1 = *(const float4*)(Al + (size_t)(k0 + e) * 8 + 4);
        acc[0] = fmaf(xv, a0.x, acc[0]); acc[1] = fmaf(xv, a0.y, acc[1]);
        acc[2] = fmaf(xv, a0.z, acc[2]); acc[3] = fmaf(xv, a0.w, acc[3]);
        acc[4] = fmaf(xv, a1.x, acc[4]); acc[5] = fmaf(xv, a1.y, acc[5]);
        acc[6] = fmaf(xv, a1.z, acc[6]); acc[7] = fmaf(xv, a1.w, acc[7]);
    }
#pragma unroll
    for (int off = 16; off > 0; off >>= 1)
#pragma unroll
        for (int r = 0; r < 8; r++)
            acc[r] += __shfl_xor_sync(0xffffffffu, acc[r], off);

    __shared__ float red[8][8];
    if ((tid & 31) == 0)
#pragma unroll
        for (int r = 0; r < 8; r++) red[tid >> 5][r] = acc[r];
    __syncthreads();
    if (tid < 8) {
        float s = 0.f;
#pragma unroll
        for (int w = 0; w < 8; w++) s += red[w][tid];
        xa[(size_t)m * 8 + tid] = s;
    }
}

// ---------------------------------------------------------------------------
// prep: W[K,N] fp32 -> Th/Tl[N,K] bf16 (transpose + split)
// ---------------------------------------------------------------------------
__global__ __launch_bounds__(256) void transpose_split(const float* __restrict__ W,
                                                       __nv_bfloat16* __restrict__ Th,
                                                       __nv_bfloat16* __restrict__ Tl,
                                                       int K, int N)
{
    __shared__ float t[32][33];
    const int n0 = blockIdx.x * 32, k0 = blockIdx.y * 32;
#pragma unroll
    for (int i = threadIdx.y; i < 32; i += 8)
        t[i][threadIdx.x] = W[(size_t)(k0 + i) * N + n0 + threadIdx.x];
    __syncthreads();
#pragma unroll
    for (int i = threadIdx.y; i < 32; i += 8) {
        float v = t[threadIdx.x][i];
        __nv_bfloat16 hh = __float2bfloat16(v);
        Th[(size_t)(n0 + i) * K + k0 + threadIdx.x] = hh;
        Tl[(size_t)(n0 + i) * K + k0 + threadIdx.x] =
            __float2bfloat16(v - __bfloat162float(hh));
    }
}

// ---------------------------------------------------------------------------
// HMMA GEMM: 512 threads (16 warps = 4 warps/SMSP), warp tile 32x32,
// 4-stage cp.async ring + register fragment double buffering.
// ---------------------------------------------------------------------------
static constexpr int TPITCH = 80;
static constexpr int TILE_B = 128 * TPITCH;          // 10240 B
static constexpr int STG_B  = 4 * TILE_B;            // 40960 B per stage
static constexpr int NSTG   = 4;
static constexpr int GSMEM  = NSTG * STG_B;          // 163840 B

__device__ __forceinline__ void ldtile_async512(uint32_t sdst,
                                                const __nv_bfloat16* __restrict__ g,
                                                int row0, int k0, int ldk, int tid)
{
    const int r = tid >> 2, c = tid & 3;
    CP_ASYNC16(sdst + r * TPITCH + c * 16,
               g + (size_t)(row0 + r) * ldk + k0 + c * 8);
}

struct Frags {                 // 32 regs: warp tile 32x32
    uint32_t ah[2][4];
    uint32_t al[2][4];
    uint32_t bh[4][2];
    uint32_t bl[4][2];
};

__device__ __forceinline__ void load_frags(Frags& f, uint32_t s0,
                                           uint32_t aOff, uint32_t bOff,
                                           uint32_t kOff)
{
#pragma unroll
    for (int mi = 0; mi < 2; mi++) {
        LDSM_X4(f.ah[mi][0], f.ah[mi][1], f.ah[mi][2], f.ah[mi][3],
                s0 + aOff + mi * 16 * TPITCH + kOff);
        LDSM_X4(f.al[mi][0], f.al[mi][1], f.al[mi][2], f.al[mi][3],
                s0 + TILE_B + aOff + mi * 16 * TPITCH + kOff);
    }
#pragma unroll
    for (int ng = 0; ng < 2; ng++) {
        uint32_t r0, r1, r2, r3;
        LDSM_X4(r0, r1, r2, r3, s0 + 2 * TILE_B + bOff + ng * 16 * TPITCH + kOff);
        f.bh[ng * 2][0] = r0; f.bh[ng * 2][1] = r2;
        f.bh[ng * 2 + 1][0] = r1; f.bh[ng * 2 + 1][1] = r3;
        LDSM_X4(r0, r1, r2, r3, s0 + 3 * TILE_B + bOff + ng * 16 * TPITCH + kOff);
        f.bl[ng * 2][0] = r0; f.bl[ng * 2][1] = r2;
        f.bl[ng * 2 + 1][0] = r1; f.bl[ng * 2 + 1][1] = r3;
    }
}

__device__ __forceinline__ void mma_all(float acc[2][4][4], const Frags& f)
{
#pragma unroll
    for (int mi = 0; mi < 2; mi++)
#pragma unroll
        for (int ni = 0; ni < 4; ni++)
            mma16816(acc[mi][ni], f.ah[mi][0], f.ah[mi][1], f.ah[mi][2], f.ah[mi][3],
                     f.bh[ni][0], f.bh[ni][1]);
#pragma unroll
    for (int mi = 0; mi < 2; mi++)
#pragma unroll
        for (int ni = 0; ni < 4; ni++)
            mma16816(acc[mi][ni], f.ah[mi][0], f.ah[mi][1], f.ah[mi][2], f.ah[mi][3],
                     f.bl[ni][0], f.bl[ni][1]);
#pragma unroll
    for (int mi = 0; mi < 2; mi++)
#pragma unroll
        for (int ni = 0; ni < 4; ni++)
            mma16816(acc[mi][ni], f.al[mi][0], f.al[mi][1], f.al[mi][2], f.al[mi][3],
                     f.bh[ni][0], f.bh[ni][1]);
}

template<bool LORA, bool SPLITOUT>
__global__ __launch_bounds__(512, 1) void gemm_mma(
    const __nv_bfloat16* __restrict__ Ah, const __nv_bfloat16* __restrict__ Al,
    const __nv_bfloat16* __restrict__ Bh, const __nv_bfloat16* __restrict__ Bl,
    const float* __restrict__ bias,
    const float* __restrict__ xa, const float* __restrict__ BlLora,
    float* __restrict__ C,
    __nv_bfloat16* __restrict__ Ch, __nv_bfloat16* __restrict__ Cl,
    int M, int N, int K)
{
    extern __shared__ char smem[];
    const uint32_t sb = smem_u32(smem);
    const int tid = threadIdx.x;
    const int warp = tid >> 5, lane = tid & 31;
    const int wm = warp & 3, wn = warp >> 2;     // 4(M) x 4(N)
    const int bn = blockIdx.x, bm = blockIdx.y;

    float acc[2][4][4];
#pragma unroll
    for (int mi = 0; mi < 2; mi++)
#pragma unroll
        for (int ni = 0; ni < 4; ni++)
#pragma unroll
            for (int e = 0; e < 4; e++) acc[mi][ni][e] = 0.f;

    const int nit = K >> 5;

    // prologue: stages 0..2
#pragma unroll
    for (int s = 0; s < NSTG - 1; s++) {
        const uint32_t sd = sb + s * STG_B;
        const int k0 = s * 32;
        ldtile_async512(sd,              Ah, bm * 128, k0, K, tid);
        ldtile_async512(sd + TILE_B,     Al, bm * 128, k0, K, tid);
        ldtile_async512(sd + 2 * TILE_B, Bh, bn * 128, k0, K, tid);
        ldtile_async512(sd + 3 * TILE_B, Bl, bn * 128, k0, K, tid);
        CP_COMMIT();
    }

    const uint32_t lrow = (uint32_t)(lane & 15) * TPITCH + (uint32_t)(lane >> 4) * 16;
    const uint32_t aOff = (wm * 32) * TPITCH + lrow;
    const uint32_t bOff = (wn * 32) * TPITCH + lrow;

    CP_WAIT(1);
    __syncthreads();

    Frags f0, f1;
    load_frags(f0, sb, aOff, bOff, 0);       // (chunk0, kk0)

    for (int it = 0; it < nit; it++) {
        if (it + NSTG - 1 < nit) {
            const uint32_t sd = sb + ((it + NSTG - 1) & (NSTG - 1)) * STG_B;
            const int k1 = (it + NSTG - 1) * 32;
            ldtile_async512(sd,              Ah, bm * 128, k1, K, tid);
            ldtile_async512(sd + TILE_B,     Al, bm * 128, k1, K, tid);
            ldtile_async512(sd + 2 * TILE_B, Bh, bn * 128, k1, K, tid);
            ldtile_async512(sd + 3 * TILE_B, Bl, bn * 128, k1, K, tid);
        }
        CP_COMMIT();     // uniform group count

        const uint32_t sCur  = sb + (it & (NSTG - 1)) * STG_B;
        const uint32_t sNext = sb + ((it + 1) & (NSTG - 1)) * STG_B;

        load_frags(f1, sCur, aOff, bOff, 32);
        mma_all(acc, f0);

        CP_WAIT(1);
        __syncthreads();

        load_frags(f0, sNext, aOff, bOff, 0);   // garbage on last iter, unused
        mma_all(acc, f1);
    }
    __syncthreads();

    float* blsm = (float*)smem;
    float* xasm = blsm + 1024;
    if (LORA) {
#pragma unroll
        for (int i = tid; i < 1024; i += 512) {
            blsm[i] = BlLora[(size_t)(i >> 7) * N + bn * 128 + (i & 127)] * 8.0f;
            xasm[i] = xa[(size_t)(bm * 128) * 8 + i];
        }
        __syncthreads();
    }

    const int g = lane >> 2, tig = lane & 3;
#pragma unroll
    for (int mi = 0; mi < 2; mi++) {
#pragma unroll
        for (int half = 0; half < 2; half++) {
            const int rloc = wm * 32 + mi * 16 + g + half * 8;
            const int grow = bm * 128 + rloc;
            float xv[8];
            if (LORA) {
#pragma unroll
                for (int r = 0; r < 8; r++) xv[r] = xasm[rloc * 8 + r];
            }
#pragma unroll
            for (int ni = 0; ni < 4; ni++) {
                const int cloc = wn * 32 + ni * 8 + tig * 2;
                float v0 = acc[mi][ni][half * 2 + 0] + bias[bn * 128 + cloc];
                float v1 = acc[mi][ni][half * 2 + 1] + bias[bn * 128 + cloc + 1];
                if (LORA) {
#pragma unroll
                    for (int r = 0; r < 8; r++) {
                        v0 = fmaf(xv[r], blsm[r * 128 + cloc],     v0);
                        v1 = fmaf(xv[r], blsm[r * 128 + cloc + 1], v1);
                    }
                }
                if (SPLITOUT) {
                    uint32_t hh, ll;
                    split2(v0, v1, hh, ll);
                    const size_t o2 = ((size_t)grow * N + bn * 128 + cloc) >> 1;
                    ((uint32_t*)Ch)[o2] = hh;
                    ((uint32_t*)Cl)[o2] = ll;
                } else {
                    float2 o; o.x = v0; o.y = v1;
                    *(float2*)(C + (size_t)grow * N + bn * 128 + cloc) = o;
                }
            }
        }
    }
}

// ---------------------------------------------------------------------------
// Flash attention (HMMA bf16 hi/lo split) — unchanged
// ---------------------------------------------------------------------------
static constexpr int FPITB = 144;
static constexpr int FTILE = 64 * FPITB;
static constexpr int FSMEM = 2 * FTILE + 2 * 4 * FTILE;

__device__ __forceinline__ void fl_tile_async(uint32_t sdst,
                                              const __nv_bfloat16* __restrict__ g,
                                              int row0, int tid)
{
#pragma unroll
    for (int i = 0; i < 4; i++) {
        const int idx = tid + i * 128;
        const int r = idx >> 3, c = idx & 7;
        CP_ASYNC16(sdst + r * FPITB + c * 16,
                   g + (size_t)(row0 + r) * 3072 + c * 8);
    }
}

__global__ __launch_bounds__(128) void flash_mma(
    const __nv_bfloat16* __restrict__ QKVh,
    const __nv_bfloat16* __restrict__ QKVl,
    __nv_bfloat16* __restrict__ Ch,
    __nv_bfloat16* __restrict__ Cl)
{
    extern __shared__ char smem[];
    const uint32_t sb = smem_u32(smem);
    const int tid = threadIdx.x, lane = tid & 31, warp = tid >> 5;
    const int qt = 31 - blockIdx.x, h = blockIdx.y, b = blockIdx.z;
    const int q0 = qt * 64;

    const __nv_bfloat16* qh_g = QKVh + (size_t)b * 2048 * 3072 + h * 64;
    const __nv_bfloat16* ql_g = QKVl + (size_t)b * 2048 * 3072 + h * 64;
    const __nv_bfloat16* kh_g = qh_g + 1024;
    const __nv_bfloat16* kl_g = ql_g + 1024;
    const __nv_bfloat16* vh_g = qh_g + 2048;
    const __nv_bfloat16* vl_g = ql_g + 2048;

    const uint32_t sQh = sb, sQl = sb + FTILE;
    const uint32_t sKV = sb + 2 * FTILE;

    fl_tile_async(sQh, qh_g, q0, tid);
    fl_tile_async(sQl, ql_g, q0, tid);
    CP_COMMIT();
    fl_tile_async(sKV,             kh_g, 0, tid);
    fl_tile_async(sKV + FTILE,     kl_g, 0, tid);
    fl_tile_async(sKV + 2 * FTILE, vh_g, 0, tid);
    fl_tile_async(sKV + 3 * FTILE, vl_g, 0, tid);
    CP_COMMIT();

    CP_WAIT(1);
    __syncthreads();

    const uint32_t lA = (uint32_t)(lane & 15) * FPITB + (uint32_t)(lane >> 4) * 16;

    uint32_t qfh[4][4], qfl[4][4];
#pragma unroll
    for (int ks = 0; ks < 4; ks++) {
        LDSM_X4(qfh[ks][0], qfh[ks][1], qfh[ks][2], qfh[ks][3],
                sQh + (warp * 16) * FPITB + lA + ks * 32);
        LDSM_X4(qfl[ks][0], qfl[ks][1], qfl[ks][2], qfl[ks][3],
                sQl + (warp * 16) * FPITB + lA + ks * 32);
    }

    float oacc[8][4];
#pragma unroll
    for (int j = 0; j < 8; j++)
#pragma unroll
        for (int e = 0; e < 4; e++) oacc[j][e] = 0.f;
    float mrow[2] = {-3.0e38f, -3.0e38f};
    float lrow[2] = {0.f, 0.f};

    const int g = lane >> 2, tig = lane & 3;

    for (int kt = 0; kt <= qt; kt++) {
        CP_WAIT(0);
        __syncthreads();

        if (kt < qt) {
            const uint32_t s1 = sKV + ((kt + 1) & 1) * (4 * FTILE);
            const int k1 = (kt + 1) * 64;
            fl_tile_async(s1,             kh_g, k1, tid);
            fl_tile_async(s1 + FTILE,     kl_g, k1, tid);
            fl_tile_async(s1 + 2 * FTILE, vh_g, k1, tid);
            fl_tile_async(s1 + 3 * FTILE, vl_g, k1, tid);
            CP_COMMIT();
        }

        const uint32_t sK = sKV + (kt & 1) * (4 * FTILE);
        const uint32_t sV = sK + 2 * FTILE;

        float sacc[8][4];
#pragma unroll
        for (int j = 0; j < 8; j++)
#pragma unroll
            for (int e = 0; e < 4; e++) sacc[j][e] = 0.f;

#pragma unroll
        for (int ks = 0; ks < 4; ks++) {
            uint32_t bh[8][2], bl[8][2];
#pragma unroll
            for (int ng = 0; ng < 4; ng++) {
                uint32_t r0, r1, r2, r3;
                LDSM_X4(r0, r1, r2, r3, sK + (ng * 16) * FPITB + lA + ks * 32);
                bh[ng * 2][0] = r0; bh[ng * 2][1] = r2;
                bh[ng * 2 + 1][0] = r1; bh[ng * 2 + 1][1] = r3;
                LDSM_X4(r0, r1, r2, r3, sK + FTILE + (ng * 16) * FPITB + lA + ks * 32);
                bl[ng * 2][0] = r0; bl[ng * 2][1] = r2;
                bl[ng * 2 + 1][0] = r1; bl[ng * 2 + 1][1] = r3;
            }
#pragma unroll
            for (int j = 0; j < 8; j++)
                mma16816(sacc[j], qfh[ks][0], qfh[ks][1], qfh[ks][2], qfh[ks][3],
                         bh[j][0], bh[j][1]);
#pragma unroll
            for (int j = 0; j < 8; j++)
                mma16816(sacc[j], qfh[ks][0], qfh[ks][1], qfh[ks][2], qfh[ks][3],
                         bl[j][0], bl[j][1]);
#pragma unroll
            for (int j = 0; j < 8; j++)
                mma16816(sacc[j], qfl[ks][0], qfl[ks][1], qfl[ks][2], qfl[ks][3],
                         bh[j][0], bh[j][1]);
        }

        if (kt == qt) {
#pragma unroll
            for (int j = 0; j < 8; j++)
#pragma unroll
                for (int e = 0; e < 4; e++) {
                    const int col = j * 8 + tig * 2 + (e & 1);
                    const int row = warp * 16 + g + ((e >> 1) << 3);
                    sacc[j][e] = (col > row) ? -1.0e30f : sacc[j][e] * 0.125f;
                }
        } else {
#pragma unroll
            for (int j = 0; j < 8; j++)
#pragma unroll
                for (int e = 0; e < 4; e++) sacc[j][e] *= 0.125f;
        }

        float tm0 = -3.0e38f, tm1 = -3.0e38f;
#pragma unroll
        for (int j = 0; j < 8; j++) {
            tm0 = fmaxf(tm0, fmaxf(sacc[j][0], sacc[j][1]));
            tm1 = fmaxf(tm1, fmaxf(sacc[j][2], sacc[j][3]));
        }
#pragma unroll
        for (int o = 1; o < 4; o <<= 1) {
            tm0 = fmaxf(tm0, __shfl_xor_sync(0xffffffffu, tm0, o));
            tm1 = fmaxf(tm1, __shfl_xor_sync(0xffffffffu, tm1, o));
        }
        const float nm0 = fmaxf(mrow[0], tm0);
        const float nm1 = fmaxf(mrow[1], tm1);
        const float c0 = __expf(mrow[0] - nm0);
        const float c1 = __expf(mrow[1] - nm1);
        mrow[0] = nm0; mrow[1] = nm1;

        float rs0 = 0.f, rs1 = 0.f;
#pragma unroll
        for (int j = 0; j < 8; j++) {
            sacc[j][0] = __expf(sacc[j][0] - nm0);
            sacc[j][1] = __expf(sacc[j][1] - nm0);
            sacc[j][2] = __expf(sacc[j][2] - nm1);
            sacc[j][3] = __expf(sacc[j][3] - nm1);
            rs0 += sacc[j][0] + sacc[j][1];
            rs1 += sacc[j][2] + sacc[j][3];
        }
#pragma unroll
        for (int o = 1; o < 4; o <<= 1) {
            rs0 += __shfl_xor_sync(0xffffffffu, rs0, o);
            rs1 += __shfl_xor_sync(0xffffffffu, rs1, o);
        }
        lrow[0] = lrow[0] * c0 + rs0;
        lrow[1] = lrow[1] * c1 + rs1;
#pragma unroll
        for (int j = 0; j < 8; j++) {
            oacc[j][0] *= c0; oacc[j][1] *= c0;
            oacc[j][2] *= c1; oacc[j][3] *= c1;
        }

#pragma unroll
        for (int t = 0; t < 4; t++) {
            uint32_t ph[4], pl[4];
            split2(sacc[2 * t][0],     sacc[2 * t][1],     ph[0], pl[0]);
            split2(sacc[2 * t][2],     sacc[2 * t][3],     ph[1], pl[1]);
            split2(sacc[2 * t + 1][0], sacc[2 * t + 1][1], ph[2], pl[2]);
            split2(sacc[2 * t + 1][2], sacc[2 * t + 1][3], ph[3], pl[3]);
            const uint32_t vrow = (uint32_t)(t * 16 + (lane & 15)) * FPITB +
                                  ((lane & 16) ? 16u : 0u);
            uint32_t vh[4][4], vl[4][4];
#pragma unroll
            for (int p = 0; p < 4; p++) {
                LDSM_X4_T(vh[p][0], vh[p][1], vh[p][2], vh[p][3],
                          sV + vrow + p * 32);
                LDSM_X4_T(vl[p][0], vl[p][1], vl[p][2], vl[p][3],
                          sV + FTILE + vrow + p * 32);
            }
#pragma unroll
            for (int p = 0; p < 4; p++) {
                mma16816(oacc[2 * p],     ph[0], ph[1], ph[2], ph[3], vh[p][0], vh[p][1]);
                mma16816(oacc[2 * p + 1], ph[0], ph[1], ph[2], ph[3], vh[p][2], vh[p][3]);
            }
#pragma unroll
            for (int p = 0; p < 4; p++) {
                mma16816(oacc[2 * p],     pl[0], pl[1], pl[2], pl[3], vh[p][0], vh[p][1]);
                mma16816(oacc[2 * p + 1], pl[0], pl[1], pl[2], pl[3], vh[p][2], vh[p][3]);
            }
#pragma unroll
            for (int p = 0; p < 4; p++) {
                mma16816(oacc[2 * p],     ph[0], ph[1], ph[2], ph[3], vl[p][0], vl[p][1]);
                mma16816(oacc[2 * p + 1], ph[0], ph[1], ph[2], ph[3], vl[p][2], vl[p][3]);
            }
        }
    }

    const float inv0 = 1.0f / lrow[0];
    const float inv1 = 1.0f / lrow[1];
    const int row0 = b * 2048 + q0 + warp * 16 + g;
#pragma unroll
    for (int j = 0; j < 8; j++) {
        const int col = h * 64 + j * 8 + tig * 2;
        uint32_t hh, ll;
        split2(oacc[j][0] * inv0, oacc[j][1] * inv0, hh, ll);
        ((uint32_t*)Ch)[((size_t)row0 * 1024 + col) >> 1] = hh;
        ((uint32_t*)Cl)[((size_t)row0 * 1024 + col) >> 1] = ll;
        split2(oacc[j][2] * inv1, oacc[j][3] * inv1, hh, ll);
        ((uint32_t*)Ch)[((size_t)(row0 + 8) * 1024 + col) >> 1] = hh;
        ((uint32_t*)Cl)[((size_t)(row0 + 8) * 1024 + col) >> 1] = ll;
    }
}

// ---------------------------------------------------------------------------
// launch
// ---------------------------------------------------------------------------
extern "C" void kernel_launch(void* const* d_in, const int* in_sizes, int n_in,
                              void* d_out, int out_size)
{
    (void)in_sizes; (void)n_in; (void)out_size;
    const float* x     = (const float*)d_in[0];
    const float* Wqkv  = (const float*)d_in[1];
    const float* bqkv  = (const float*)d_in[2];
    const float* Alora = (const float*)d_in[3];
    const float* Blora = (const float*)d_in[4];
    const float* Wproj = (const float*)d_in[5];
    const float* bproj = (const float*)d_in[6];
    float* out = (float*)d_out;

    float* xa;
    __nv_bfloat16 *xh, *xl, *wqh, *wql, *wph, *wpl, *qh, *ql, *ch, *cl;
    cudaGetSymbolAddress((void**)&xa,  g_xa);
    cudaGetSymbolAddress((void**)&xh,  g_xh);
    cudaGetSymbolAddress((void**)&xl,  g_xl);
    cudaGetSymbolAddress((void**)&wqh, g_wqh);
    cudaGetSymbolAddress((void**)&wql, g_wql);
    cudaGetSymbolAddress((void**)&wph, g_wph);
    cudaGetSymbolAddress((void**)&wpl, g_wpl);
    cudaGetSymbolAddress((void**)&qh,  g_qh);
    cudaGetSymbolAddress((void**)&ql,  g_ql);
    cudaGetSymbolAddress((void**)&ch,  g_ch);
    cudaGetSymbolAddress((void**)&cl,  g_cl);

    cudaFuncSetAttribute(gemm_mma<true, true>,
                         cudaFuncAttributeMaxDynamicSharedMemorySize, GSMEM);
    cudaFuncSetAttribute(gemm_mma<false, false>,
                         cudaFuncAttributeMaxDynamicSharedMemorySize, GSMEM);
    cudaFuncSetAttribute(flash_mma,
                         cudaFuncAttributeMaxDynamicSharedMemorySize, FSMEM);

    split_xa<<<4096, 256>>>((const float4*)x, Alora,
                            (__nv_bfloat162*)xh, (__nv_bfloat162*)xl, xa);
    transpose_split<<<dim3(96, 32), dim3(32, 8)>>>(Wqkv, wqh, wql, 1024, 3072);
    transpose_split<<<dim3(32, 32), dim3(32, 8)>>>(Wproj, wph, wpl, 1024, 1024);

    gemm_mma<true, true><<<dim3(24, 32), 512, GSMEM>>>(
        xh, xl, wqh, wql, bqkv, xa, Blora,
        nullptr, qh, ql, 4096, 3072, 1024);

    flash_mma<<<dim3(32, 16, 2), 128, FSMEM>>>(qh, ql, ch, cl);

    gemm_mma<false, false><<<dim3(8, 32), 512, GSMEM>>>(
        ch, cl, wph, wpl, bproj, nullptr, nullptr,
        out, nullptr, nullptr, 4096, 1024, 1024);
}

// round 15
// speedup vs baseline: 1.0058x; 1.0058x over previous
#include <cuda_runtime.h>
#include <cuda_bf16.h>
#include <cstdint>

// ---------------------------------------------------------------------------
// B=2, S=2048, D=1024, H=16, HD=64, RANK=8, ALPHA=8
// ---------------------------------------------------------------------------

__device__ __align__(256) float g_xa [4096 * 8];
__device__ __align__(256) __nv_bfloat16 g_xh [4096 * 1024];
__device__ __align__(256) __nv_bfloat16 g_xl [4096 * 1024];
__device__ __align__(256) __nv_bfloat16 g_wqh[3072 * 1024];
__device__ __align__(256) __nv_bfloat16 g_wql[3072 * 1024];
__device__ __align__(256) __nv_bfloat16 g_wph[1024 * 1024];
__device__ __align__(256) __nv_bfloat16 g_wpl[1024 * 1024];
__device__ __align__(256) __nv_bfloat16 g_qh [4096 * 3072];
__device__ __align__(256) __nv_bfloat16 g_ql [4096 * 3072];
__device__ __align__(256) __nv_bfloat16 g_ch [4096 * 1024];
__device__ __align__(256) __nv_bfloat16 g_cl [4096 * 1024];

// ------------------------------ asm helpers --------------------------------
__device__ __forceinline__ uint32_t smem_u32(const void* p) {
    uint32_t a;
    asm("{ .reg .u64 t; cvta.to.shared.u64 t, %1; cvt.u32.u64 %0, t; }"
        : "=r"(a) : "l"(p));
    return a;
}
#define LDSM_X4(r0, r1, r2, r3, addr)                                     \
    asm volatile("ldmatrix.sync.aligned.m8n8.x4.shared.b16 "              \
                 "{%0,%1,%2,%3}, [%4];"                                   \
                 : "=r"(r0), "=r"(r1), "=r"(r2), "=r"(r3) : "r"(addr))
#define LDSM_X4_T(r0, r1, r2, r3, addr)                                   \
    asm volatile("ldmatrix.sync.aligned.m8n8.x4.trans.shared.b16 "        \
                 "{%0,%1,%2,%3}, [%4];"                                   \
                 : "=r"(r0), "=r"(r1), "=r"(r2), "=r"(r3) : "r"(addr))
#define CP_ASYNC16(dst, src)                                              \
    asm volatile("cp.async.cg.shared.global [%0], [%1], 16;"              \
                 :: "r"(dst), "l"(src))
#define CP_COMMIT()  asm volatile("cp.async.commit_group;")
#define CP_WAIT(n)   asm volatile("cp.async.wait_group %0;" :: "n"(n))

__device__ __forceinline__ void mma16816(float* c,
                                         uint32_t a0, uint32_t a1,
                                         uint32_t a2, uint32_t a3,
                                         uint32_t b0, uint32_t b1)
{
    asm volatile(
        "mma.sync.aligned.m16n8k16.row.col.f32.bf16.bf16.f32 "
        "{%0,%1,%2,%3}, {%4,%5,%6,%7}, {%8,%9}, {%0,%1,%2,%3};"
        : "+f"(c[0]), "+f"(c[1]), "+f"(c[2]), "+f"(c[3])
        : "r"(a0), "r"(a1), "r"(a2), "r"(a3), "r"(b0), "r"(b1));
}

__device__ __forceinline__ void split2(float x, float y, uint32_t& h, uint32_t& l)
{
    __nv_bfloat16 hx = __float2bfloat16(x);
    __nv_bfloat16 hy = __float2bfloat16(y);
    __nv_bfloat16 lx = __float2bfloat16(x - __bfloat162float(hx));
    __nv_bfloat16 ly = __float2bfloat16(y - __bfloat162float(hy));
    __nv_bfloat162 hp, lp;
    hp.x = hx; hp.y = hy;
    lp.x = lx; lp.y = ly;
    h = *(uint32_t*)&hp;
    l = *(uint32_t*)&lp;
}

// ---------------------------------------------------------------------------
// fused prep for x: bf16 hi/lo split + xa = x @ A_lora
// ---------------------------------------------------------------------------
__global__ __launch_bounds__(256) void split_xa(const float4* __restrict__ x,
                                                const float* __restrict__ Al,
                                                __nv_bfloat162* __restrict__ h,
                                                __nv_bfloat162* __restrict__ l,
                                                float* __restrict__ xa)
{
    const int m = blockIdx.x, tid = threadIdx.x;
    const int i = m * 256 + tid;
    float4 v = x[i];
    uint32_t h0, l0, h1, l1;
    split2(v.x, v.y, h0, l0);
    split2(v.z, v.w, h1, l1);
    h[2 * i]     = *(__nv_bfloat162*)&h0;
    h[2 * i + 1] = *(__nv_bfloat162*)&h1;
    l[2 * i]     = *(__nv_bfloat162*)&l0;
    l[2 * i + 1] = *(__nv_bfloat162*)&l1;

    float acc[8];
#pragma unroll
    for (int r = 0; r < 8; r++) acc[r] = 0.f;
    const int k0 = tid * 4;
    const float* vv = &v.x;
#pragma unroll
    for (int e = 0; e < 4; e++) {
        const float xv = vv[e];
        const float4 a0 = *(const float4*)(Al + (size_t)(k0 + e) * 8);
        const float4 a1 = *(const float4*)(Al + (size_t)(k0 + e) * 8 + 4);
        acc[0] = fmaf(xv, a0.x, acc[0]); acc[1] = fmaf(xv, a0.y, acc[1]);
        acc[2] = fmaf(xv, a0.z, acc[2]); acc[3] = fmaf(xv, a0.w, acc[3]);
        acc[4] = fmaf(xv, a1.x, acc[4]); acc[5] = fmaf(xv, a1.y, acc[5]);
        acc[6] = fmaf(xv, a1.z, acc[6]); acc[7] = fmaf(xv, a1.w, acc[7]);
    }
#pragma unroll
    for (int off = 16; off > 0; off >>= 1)
#pragma unroll
        for (int r = 0; r < 8; r++)
            acc[r] += __shfl_xor_sync(0xffffffffu, acc[r], off);

    __shared__ float red[8][8];
    if ((tid & 31) == 0)
#pragma unroll
        for (int r = 0; r < 8; r++) red[tid >> 5][r] = acc[r];
    __syncthreads();
    if (tid < 8) {
        float s = 0.f;
#pragma unroll
        for (int w = 0; w < 8; w++) s += red[w][tid];
        xa[(size_t)m * 8 + tid] = s;
    }
}

// ---------------------------------------------------------------------------
// prep: W[K,N] fp32 -> Th/Tl[N,K] bf16 (transpose + split)
// ---------------------------------------------------------------------------
__global__ __launch_bounds__(256) void transpose_split(const float* __restrict__ W,
                                                       __nv_bfloat16* __restrict__ Th,
                                                       __nv_bfloat16* __restrict__ Tl,
                                                       int K, int N)
{
    __shared__ float t[32][33];
    const int n0 = blockIdx.x * 32, k0 = blockIdx.y * 32;
#pragma unroll
    for (int i = threadIdx.y; i < 32; i += 8)
        t[i][threadIdx.x] = W[(size_t)(k0 + i) * N + n0 + threadIdx.x];
    __syncthreads();
#pragma unroll
    for (int i = threadIdx.y; i < 32; i += 8) {
        float v = t[threadIdx.x][i];
        __nv_bfloat16 hh = __float2bfloat16(v);
        Th[(size_t)(n0 + i) * K + k0 + threadIdx.x] = hh;
        Tl[(size_t)(n0 + i) * K + k0 + threadIdx.x] =
            __float2bfloat16(v - __bfloat162float(hh));
    }
}

// ---------------------------------------------------------------------------
// HMMA GEMM: 512 threads (16 warps = 4 warps/SMSP), warp tile 32x32,
// 4-stage cp.async ring + register fragment double buffering.
// ---------------------------------------------------------------------------
static constexpr int TPITCH = 80;
static constexpr int TILE_B = 128 * TPITCH;          // 10240 B
static constexpr int STG_B  = 4 * TILE_B;            // 40960 B per stage
static constexpr int NSTG   = 4;
static constexpr int GSMEM  = NSTG * STG_B;          // 163840 B

__device__ __forceinline__ void ldtile_async512(uint32_t sdst,
                                                const __nv_bfloat16* __restrict__ g,
                                                int row0, int k0, int ldk, int tid)
{
    const int r = tid >> 2, c = tid & 3;
    CP_ASYNC16(sdst + r * TPITCH + c * 16,
               g + (size_t)(row0 + r) * ldk + k0 + c * 8);
}

struct Frags {                 // 32 regs: warp tile 32x32
    uint32_t ah[2][4];
    uint32_t al[2][4];
    uint32_t bh[4][2];
    uint32_t bl[4][2];
};

__device__ __forceinline__ void load_frags(Frags& f, uint32_t s0,
                                           uint32_t aOff, uint32_t bOff,
                                           uint32_t kOff)
{
#pragma unroll
    for (int mi = 0; mi < 2; mi++) {
        LDSM_X4(f.ah[mi][0], f.ah[mi][1], f.ah[mi][2], f.ah[mi][3],
                s0 + aOff + mi * 16 * TPITCH + kOff);
        LDSM_X4(f.al[mi][0], f.al[mi][1], f.al[mi][2], f.al[mi][3],
                s0 + TILE_B + aOff + mi * 16 * TPITCH + kOff);
    }
#pragma unroll
    for (int ng = 0; ng < 2; ng++) {
        uint32_t r0, r1, r2, r3;
        LDSM_X4(r0, r1, r2, r3, s0 + 2 * TILE_B + bOff + ng * 16 * TPITCH + kOff);
        f.bh[ng * 2][0] = r0; f.bh[ng * 2][1] = r2;
        f.bh[ng * 2 + 1][0] = r1; f.bh[ng * 2 + 1][1] = r3;
        LDSM_X4(r0, r1, r2, r3, s0 + 3 * TILE_B + bOff + ng * 16 * TPITCH + kOff);
        f.bl[ng * 2][0] = r0; f.bl[ng * 2][1] = r2;
        f.bl[ng * 2 + 1][0] = r1; f.bl[ng * 2 + 1][1] = r3;
    }
}

__device__ __forceinline__ void mma_all(float acc[2][4][4], const Frags& f)
{
#pragma unroll
    for (int mi = 0; mi < 2; mi++)
#pragma unroll
        for (int ni = 0; ni < 4; ni++)
            mma16816(acc[mi][ni], f.ah[mi][0], f.ah[mi][1], f.ah[mi][2], f.ah[mi][3],
                     f.bh[ni][0], f.bh[ni][1]);
#pragma unroll
    for (int mi = 0; mi < 2; mi++)
#pragma unroll
        for (int ni = 0; ni < 4; ni++)
            mma16816(acc[mi][ni], f.ah[mi][0], f.ah[mi][1], f.ah[mi][2], f.ah[mi][3],
                     f.bl[ni][0], f.bl[ni][1]);
#pragma unroll
    for (int mi = 0; mi < 2; mi++)
#pragma unroll
        for (int ni = 0; ni < 4; ni++)
            mma16816(acc[mi][ni], f.al[mi][0], f.al[mi][1], f.al[mi][2], f.al[mi][3],
                     f.bh[ni][0], f.bh[ni][1]);
}

template<bool LORA, bool SPLITOUT>
__global__ __launch_bounds__(512, 1) void gemm_mma(
    const __nv_bfloat16* __restrict__ Ah, const __nv_bfloat16* __restrict__ Al,
    const __nv_bfloat16* __restrict__ Bh, const __nv_bfloat16* __restrict__ Bl,
    const float* __restrict__ bias,
    const float* __restrict__ xa, const float* __restrict__ BlLora,
    float* __restrict__ C,
    __nv_bfloat16* __restrict__ Ch, __nv_bfloat16* __restrict__ Cl,
    int M, int N, int K)
{
    extern __shared__ char smem[];
    const uint32_t sb = smem_u32(smem);
    const int tid = threadIdx.x;
    const int warp = tid >> 5, lane = tid & 31;
    const int wm = warp & 3, wn = warp >> 2;     // 4(M) x 4(N)
    const int bn = blockIdx.x, bm = blockIdx.y;

    float acc[2][4][4];
#pragma unroll
    for (int mi = 0; mi < 2; mi++)
#pragma unroll
        for (int ni = 0; ni < 4; ni++)
#pragma unroll
            for (int e = 0; e < 4; e++) acc[mi][ni][e] = 0.f;

    const int nit = K >> 5;

    // prologue: stages 0..2
#pragma unroll
    for (int s = 0; s < NSTG - 1; s++) {
        const uint32_t sd = sb + s * STG_B;
        const int k0 = s * 32;
        ldtile_async512(sd,              Ah, bm * 128, k0, K, tid);
        ldtile_async512(sd + TILE_B,     Al, bm * 128, k0, K, tid);
        ldtile_async512(sd + 2 * TILE_B, Bh, bn * 128, k0, K, tid);
        ldtile_async512(sd + 3 * TILE_B, Bl, bn * 128, k0, K, tid);
        CP_COMMIT();
    }

    const uint32_t lrow = (uint32_t)(lane & 15) * TPITCH + (uint32_t)(lane >> 4) * 16;
    const uint32_t aOff = (wm * 32) * TPITCH + lrow;
    const uint32_t bOff = (wn * 32) * TPITCH + lrow;

    CP_WAIT(1);
    __syncthreads();

    Frags f0, f1;
    load_frags(f0, sb, aOff, bOff, 0);       // (chunk0, kk0)

    for (int it = 0; it < nit; it++) {
        if (it + NSTG - 1 < nit) {
            const uint32_t sd = sb + ((it + NSTG - 1) & (NSTG - 1)) * STG_B;
            const int k1 = (it + NSTG - 1) * 32;
            ldtile_async512(sd,              Ah, bm * 128, k1, K, tid);
            ldtile_async512(sd + TILE_B,     Al, bm * 128, k1, K, tid);
            ldtile_async512(sd + 2 * TILE_B, Bh, bn * 128, k1, K, tid);
            ldtile_async512(sd + 3 * TILE_B, Bl, bn * 128, k1, K, tid);
        }
        CP_COMMIT();     // uniform group count

        const uint32_t sCur  = sb + (it & (NSTG - 1)) * STG_B;
        const uint32_t sNext = sb + ((it + 1) & (NSTG - 1)) * STG_B;

        load_frags(f1, sCur, aOff, bOff, 32);
        mma_all(acc, f0);

        CP_WAIT(1);
        __syncthreads();

        load_frags(f0, sNext, aOff, bOff, 0);   // garbage on last iter, unused
        mma_all(acc, f1);
    }
    __syncthreads();

    float* blsm = (float*)smem;
    float* xasm = blsm + 1024;
    if (LORA) {
#pragma unroll
        for (int i = tid; i < 1024; i += 512) {
            blsm[i] = BlLora[(size_t)(i >> 7) * N + bn * 128 + (i & 127)] * 8.0f;
            xasm[i] = xa[(size_t)(bm * 128) * 8 + i];
        }
        __syncthreads();
    }

    const int g = lane >> 2, tig = lane & 3;
#pragma unroll
    for (int mi = 0; mi < 2; mi++) {
#pragma unroll
        for (int half = 0; half < 2; half++) {
            const int rloc = wm * 32 + mi * 16 + g + half * 8;
            const int grow = bm * 128 + rloc;
            float xv[8];
            if (LORA) {
#pragma unroll
                for (int r = 0; r < 8; r++) xv[r] = xasm[rloc * 8 + r];
            }
#pragma unroll
            for (int ni = 0; ni < 4; ni++) {
                const int cloc = wn * 32 + ni * 8 + tig * 2;
                float v0 = acc[mi][ni][half * 2 + 0] + bias[bn * 128 + cloc];
                float v1 = acc[mi][ni][half * 2 + 1] + bias[bn * 128 + cloc + 1];
                if (LORA) {
#pragma unroll
                    for (int r = 0; r < 8; r++) {
                        v0 = fmaf(xv[r], blsm[r * 128 + cloc],     v0);
                        v1 = fmaf(xv[r], blsm[r * 128 + cloc + 1], v1);
                    }
                }
                if (SPLITOUT) {
                    uint32_t hh, ll;
                    split2(v0, v1, hh, ll);
                    const size_t o2 = ((size_t)grow * N + bn * 128 + cloc) >> 1;
                    ((uint32_t*)Ch)[o2] = hh;
                    ((uint32_t*)Cl)[o2] = ll;
                } else {
                    float2 o; o.x = v0; o.y = v1;
                    *(float2*)(C + (size_t)grow * N + bn * 128 + cloc) = o;
                }
            }
        }
    }
}

// ---------------------------------------------------------------------------
// Flash attention (HMMA bf16 hi/lo split) — unchanged
// ---------------------------------------------------------------------------
static constexpr int FPITB = 144;
static constexpr int FTILE = 64 * FPITB;
static constexpr int FSMEM = 2 * FTILE + 2 * 4 * FTILE;

__device__ __forceinline__ void fl_tile_async(uint32_t sdst,
                                              const __nv_bfloat16* __restrict__ g,
                                              int row0, int tid)
{
#pragma unroll
    for (int i = 0; i < 4; i++) {
        const int idx = tid + i * 128;
        const int r = idx >> 3, c = idx & 7;
        CP_ASYNC16(sdst + r * FPITB + c * 16,
                   g + (size_t)(row0 + r) * 3072 + c * 8);
    }
}

__global__ __launch_bounds__(128) void flash_mma(
    const __nv_bfloat16* __restrict__ QKVh,
    const __nv_bfloat16* __restrict__ QKVl,
    __nv_bfloat16* __restrict__ Ch,
    __nv_bfloat16* __restrict__ Cl)
{
    extern __shared__ char smem[];
    const uint32_t sb = smem_u32(smem);
    const int tid = threadIdx.x, lane = tid & 31, warp = tid >> 5;
    const int qt = 31 - blockIdx.x, h = blockIdx.y, b = blockIdx.z;
    const int q0 = qt * 64;

    const __nv_bfloat16* qh_g = QKVh + (size_t)b * 2048 * 3072 + h * 64;
    const __nv_bfloat16* ql_g = QKVl + (size_t)b * 2048 * 3072 + h * 64;
    const __nv_bfloat16* kh_g = qh_g + 1024;
    const __nv_bfloat16* kl_g = ql_g + 1024;
    const __nv_bfloat16* vh_g = qh_g + 2048;
    const __nv_bfloat16* vl_g = ql_g + 2048;

    const uint32_t sQh = sb, sQl = sb + FTILE;
    const uint32_t sKV = sb + 2 * FTILE;

    fl_tile_async(sQh, qh_g, q0, tid);
    fl_tile_async(sQl, ql_g, q0, tid);
    CP_COMMIT();
    fl_tile_async(sKV,             kh_g, 0, tid);
    fl_tile_async(sKV + FTILE,     kl_g, 0, tid);
    fl_tile_async(sKV + 2 * FTILE, vh_g, 0, tid);
    fl_tile_async(sKV + 3 * FTILE, vl_g, 0, tid);
    CP_COMMIT();

    CP_WAIT(1);
    __syncthreads();

    const uint32_t lA = (uint32_t)(lane & 15) * FPITB + (uint32_t)(lane >> 4) * 16;

    uint32_t qfh[4][4], qfl[4][4];
#pragma unroll
    for (int ks = 0; ks < 4; ks++) {
        LDSM_X4(qfh[ks][0], qfh[ks][1], qfh[ks][2], qfh[ks][3],
                sQh + (warp * 16) * FPITB + lA + ks * 32);
        LDSM_X4(qfl[ks][0], qfl[ks][1], qfl[ks][2], qfl[ks][3],
                sQl + (warp * 16) * FPITB + lA + ks * 32);
    }

    float oacc[8][4];
#pragma unroll
    for (int j = 0; j < 8; j++)
#pragma unroll
        for (int e = 0; e < 4; e++) oacc[j][e] = 0.f;
    float mrow[2] = {-3.0e38f, -3.0e38f};
    float lrow[2] = {0.f, 0.f};

    const int g = lane >> 2, tig = lane & 3;

    for (int kt = 0; kt <= qt; kt++) {
        CP_WAIT(0);
        __syncthreads();

        if (kt < qt) {
            const uint32_t s1 = sKV + ((kt + 1) & 1) * (4 * FTILE);
            const int k1 = (kt + 1) * 64;
            fl_tile_async(s1,             kh_g, k1, tid);
            fl_tile_async(s1 + FTILE,     kl_g, k1, tid);
            fl_tile_async(s1 + 2 * FTILE, vh_g, k1, tid);
            fl_tile_async(s1 + 3 * FTILE, vl_g, k1, tid);
            CP_COMMIT();
        }

        const uint32_t sK = sKV + (kt & 1) * (4 * FTILE);
        const uint32_t sV = sK + 2 * FTILE;

        float sacc[8][4];
#pragma unroll
        for (int j = 0; j < 8; j++)
#pragma unroll
            for (int e = 0; e < 4; e++) sacc[j][e] = 0.f;

#pragma unroll
        for (int ks = 0; ks < 4; ks++) {
            uint32_t bh[8][2], bl[8][2];
#pragma unroll
            for (int ng = 0; ng < 4; ng++) {
                uint32_t r0, r1, r2, r3;
                LDSM_X4(r0, r1, r2, r3, sK + (ng * 16) * FPITB + lA + ks * 32);
                bh[ng * 2][0] = r0; bh[ng * 2][1] = r2;
                bh[ng * 2 + 1][0] = r1; bh[ng * 2 + 1][1] = r3;
                LDSM_X4(r0, r1, r2, r3, sK + FTILE + (ng * 16) * FPITB + lA + ks * 32);
                bl[ng * 2][0] = r0; bl[ng * 2][1] = r2;
                bl[ng * 2 + 1][0] = r1; bl[ng * 2 + 1][1] = r3;
            }
#pragma unroll
            for (int j = 0; j < 8; j++)
                mma16816(sacc[j], qfh[ks][0], qfh[ks][1], qfh[ks][2], qfh[ks][3],
                         bh[j][0], bh[j][1]);
#pragma unroll
            for (int j = 0; j < 8; j++)
                mma16816(sacc[j], qfh[ks][0], qfh[ks][1], qfh[ks][2], qfh[ks][3],
                         bl[j][0], bl[j][1]);
#pragma unroll
            for (int j = 0; j < 8; j++)
                mma16816(sacc[j], qfl[ks][0], qfl[ks][1], qfl[ks][2], qfl[ks][3],
                         bh[j][0], bh[j][1]);
        }

        if (kt == qt) {
#pragma unroll
            for (int j = 0; j < 8; j++)
#pragma unroll
                for (int e = 0; e < 4; e++) {
                    const int col = j * 8 + tig * 2 + (e & 1);
                    const int row = warp * 16 + g + ((e >> 1) << 3);
                    sacc[j][e] = (col > row) ? -1.0e30f : sacc[j][e] * 0.125f;
                }
        } else {
#pragma unroll
            for (int j = 0; j < 8; j++)
#pragma unroll
                for (int e = 0; e < 4; e++) sacc[j][e] *= 0.125f;
        }

        float tm0 = -3.0e38f, tm1 = -3.0e38f;
#pragma unroll
        for (int j = 0; j < 8; j++) {
            tm0 = fmaxf(tm0, fmaxf(sacc[j][0], sacc[j][1]));
            tm1 = fmaxf(tm1, fmaxf(sacc[j][2], sacc[j][3]));
        }
#pragma unroll
        for (int o = 1; o < 4; o <<= 1) {
            tm0 = fmaxf(tm0, __shfl_xor_sync(0xffffffffu, tm0, o));
            tm1 = fmaxf(tm1, __shfl_xor_sync(0xffffffffu, tm1, o));
        }
        const float nm0 = fmaxf(mrow[0], tm0);
        const float nm1 = fmaxf(mrow[1], tm1);
        const float c0 = __expf(mrow[0] - nm0);
        const float c1 = __expf(mrow[1] - nm1);
        mrow[0] = nm0; mrow[1] = nm1;

        float rs0 = 0.f, rs1 = 0.f;
#pragma unroll
        for (int j = 0; j < 8; j++) {
            sacc[j][0] = __expf(sacc[j][0] - nm0);
            sacc[j][1] = __expf(sacc[j][1] - nm0);
            sacc[j][2] = __expf(sacc[j][2] - nm1);
            sacc[j][3] = __expf(sacc[j][3] - nm1);
            rs0 += sacc[j][0] + sacc[j][1];
            rs1 += sacc[j][2] + sacc[j][3];
        }
#pragma unroll
        for (int o = 1; o < 4; o <<= 1) {
            rs0 += __shfl_xor_sync(0xffffffffu, rs0, o);
            rs1 += __shfl_xor_sync(0xffffffffu, rs1, o);
        }
        lrow[0] = lrow[0] * c0 + rs0;
        lrow[1] = lrow[1] * c1 + rs1;
#pragma unroll
        for (int j = 0; j < 8; j++) {
            oacc[j][0] *= c0; oacc[j][1] *= c0;
            oacc[j][2] *= c1; oacc[j][3] *= c1;
        }

#pragma unroll
        for (int t = 0; t < 4; t++) {
            uint32_t ph[4], pl[4];
            split2(sacc[2 * t][0],     sacc[2 * t][1],     ph[0], pl[0]);
            split2(sacc[2 * t][2],     sacc[2 * t][3],     ph[1], pl[1]);
            split2(sacc[2 * t + 1][0], sacc[2 * t + 1][1], ph[2], pl[2]);
            split2(sacc[2 * t + 1][2], sacc[2 * t + 1][3], ph[3], pl[3]);
            const uint32_t vrow = (uint32_t)(t * 16 + (lane & 15)) * FPITB +
                                  ((lane & 16) ? 16u : 0u);
            uint32_t vh[4][4], vl[4][4];
#pragma unroll
            for (int p = 0; p < 4; p++) {
                LDSM_X4_T(vh[p][0], vh[p][1], vh[p][2], vh[p][3],
                          sV + vrow + p * 32);
                LDSM_X4_T(vl[p][0], vl[p][1], vl[p][2], vl[p][3],
                          sV + FTILE + vrow + p * 32);
            }
#pragma unroll
            for (int p = 0; p < 4; p++) {
                mma16816(oacc[2 * p],     ph[0], ph[1], ph[2], ph[3], vh[p][0], vh[p][1]);
                mma16816(oacc[2 * p + 1], ph[0], ph[1], ph[2], ph[3], vh[p][2], vh[p][3]);
            }
#pragma unroll
            for (int p = 0; p < 4; p++) {
                mma16816(oacc[2 * p],     pl[0], pl[1], pl[2], pl[3], vh[p][0], vh[p][1]);
                mma16816(oacc[2 * p + 1], pl[0], pl[1], pl[2], pl[3], vh[p][2], vh[p][3]);
            }
#pragma unroll
            for (int p = 0; p < 4; p++) {
                mma16816(oacc[2 * p],     ph[0], ph[1], ph[2], ph[3], vl[p][0], vl[p][1]);
                mma16816(oacc[2 * p + 1], ph[0], ph[1], ph[2], ph[3], vl[p][2], vl[p][3]);
            }
        }
    }

    const float inv0 = 1.0f / lrow[0];
    const float inv1 = 1.0f / lrow[1];
    const int row0 = b * 2048 + q0 + warp * 16 + g;
#pragma unroll
    for (int j = 0; j < 8; j++) {
        const int col = h * 64 + j * 8 + tig * 2;
        uint32_t hh, ll;
        split2(oacc[j][0] * inv0, oacc[j][1] * inv0, hh, ll);
        ((uint32_t*)Ch)[((size_t)row0 * 1024 + col) >> 1] = hh;
        ((uint32_t*)Cl)[((size_t)row0 * 1024 + col) >> 1] = ll;
        split2(oacc[j][2] * inv1, oacc[j][3] * inv1, hh, ll);
        ((uint32_t*)Ch)[((size_t)(row0 + 8) * 1024 + col) >> 1] = hh;
        ((uint32_t*)Cl)[((size_t)(row0 + 8) * 1024 + col) >> 1] = ll;
    }
}

// ---------------------------------------------------------------------------
// launch
// ---------------------------------------------------------------------------
extern "C" void kernel_launch(void* const* d_in, const int* in_sizes, int n_in,
                              void* d_out, int out_size)
{
    (void)in_sizes; (void)n_in; (void)out_size;
    const float* x     = (const float*)d_in[0];
    const float* Wqkv  = (const float*)d_in[1];
    const float* bqkv  = (const float*)d_in[2];
    const float* Alora = (const float*)d_in[3];
    const float* Blora = (const float*)d_in[4];
    const float* Wproj = (const float*)d_in[5];
    const float* bproj = (const float*)d_in[6];
    float* out = (float*)d_out;

    float* xa;
    __nv_bfloat16 *xh, *xl, *wqh, *wql, *wph, *wpl, *qh, *ql, *ch, *cl;
    cudaGetSymbolAddress((void**)&xa,  g_xa);
    cudaGetSymbolAddress((void**)&xh,  g_xh);
    cudaGetSymbolAddress((void**)&xl,  g_xl);
    cudaGetSymbolAddress((void**)&wqh, g_wqh);
    cudaGetSymbolAddress((void**)&wql, g_wql);
    cudaGetSymbolAddress((void**)&wph, g_wph);
    cudaGetSymbolAddress((void**)&wpl, g_wpl);
    cudaGetSymbolAddress((void**)&qh,  g_qh);
    cudaGetSymbolAddress((void**)&ql,  g_ql);
    cudaGetSymbolAddress((void**)&ch,  g_ch);
    cudaGetSymbolAddress((void**)&cl,  g_cl);

    cudaFuncSetAttribute(gemm_mma<true, true>,
                         cudaFuncAttributeMaxDynamicSharedMemorySize, GSMEM);
    cudaFuncSetAttribute(gemm_mma<false, false>,
                         cudaFuncAttributeMaxDynamicSharedMemorySize, GSMEM);
    cudaFuncSetAttribute(flash_mma,
                         cudaFuncAttributeMaxDynamicSharedMemorySize, FSMEM);

    split_xa<<<4096, 256>>>((const float4*)x, Alora,
                            (__nv_bfloat162*)xh, (__nv_bfloat162*)xl, xa);
    transpose_split<<<dim3(96, 32), dim3(32, 8)>>>(Wqkv, wqh, wql, 1024, 3072);
    transpose_split<<<dim3(32, 32), dim3(32, 8)>>>(Wproj, wph, wpl, 1024, 1024);

    gemm_mma<true, true><<<dim3(24, 32), 512, GSMEM>>>(
        xh, xl, wqh, wql, bqkv, xa, Blora,
        nullptr, qh, ql, 4096, 3072, 1024);

    flash_mma<<<dim3(32, 16, 2), 128, FSMEM>>>(qh, ql, ch, cl);

    gemm_mma<false, false><<<dim3(8, 32), 512, GSMEM>>>(
        ch, cl, wph, wpl, bproj, nullptr, nullptr,
        out, nullptr, nullptr, 4096, 1024, 1024);
}